// round 17
// baseline (speedup 1.0000x reference)
#include <cuda_runtime.h>
#include <cuda_fp16.h>
#include <cstdint>

// ---------------------------------------------------------------------------
// Problem constants
// ---------------------------------------------------------------------------
#define IN_F    4096
#define OUT_F   16384
#define ACT_IN  2048
#define ACT_OUT 8192
#define NROWS   8192      // B*S

// GEMM tiling: CTA 128(M) x 128(N), 8 warps as 2(M) x 4(N), warp tile 64x32.
// 2 CTAs per SM (<=128 regs/thread, 96 KB smem/CTA) so one CTA's barriers
// and epilogue overlap the other CTA's MMA stream.
#define BM 128
#define BN 128
#define KC 64                    // K elements per stage
#define NSTAGE (ACT_IN / KC)     // 32
#define NTH 256
#define NBUF 3                   // cp.async pipeline depth

// SMEM per stage: A 16K | B 16K = 32 KB; 3 stages = 96 KB
#define T_A 0
#define T_B 16384
#define STAGE_BYTES 32768
#define SMEM_TOTAL  (NBUF * STAGE_BYTES)   // 98304

// Epilogue staging: C tile [BM][SC_PITCH] fp32 = 67.5 KB <= 96 KB
#define SC_PITCH 132

// fp16 operand scratch (allocation-free rule: __device__ globals).
__device__ __half g_A[(size_t)NROWS * ACT_IN];
__device__ __half g_B[(size_t)ACT_OUT * ACT_IN];
// Inverse output map: g_inv[c] = n+1 if out_idx[n]==c else 0.
__device__ int g_inv[OUT_F];

// ---------------------------------------------------------------------------
// PTX helpers (sm_80-baseline only — harness lowers through plain compute_103)
// ---------------------------------------------------------------------------
__device__ __forceinline__ uint32_t smem_u32(const void* p) {
    uint32_t a;
    asm("{ .reg .u64 t; cvta.to.shared.u64 t, %1; cvt.u32.u64 %0, t; }"
        : "=r"(a) : "l"(p));
    return a;
}

#define SWZ(o) ((o) ^ (((o) >> 3) & 0x70))   // SW128 xor swizzle (16B granules)

#define CPA16(sa, gp) \
    asm volatile("cp.async.cg.shared.global [%0], [%1], 16;" :: "r"(sa), "l"(gp) : "memory")
#define CPA_COMMIT() asm volatile("cp.async.commit_group;" ::: "memory")
#define CPA_WAIT(n)  asm volatile("cp.async.wait_group %0;" :: "n"(n) : "memory")

#define LDSM4(r0, r1, r2, r3, a) \
    asm volatile("ldmatrix.sync.aligned.m8n8.x4.shared.b16 {%0,%1,%2,%3}, [%4];" \
                 : "=r"(r0), "=r"(r1), "=r"(r2), "=r"(r3) : "r"(a))

// D += A*B, fp16 in, fp32 accum.  A frag 4xb32, B frag 2xb32, C 4xf32.
#define MMA(c, a0, a1, a2, a3, b0, b1) \
    asm volatile("mma.sync.aligned.m16n8k16.row.col.f32.f16.f16.f32 " \
                 "{%0,%1,%2,%3}, {%4,%5,%6,%7}, {%8,%9}, {%0,%1,%2,%3};" \
                 : "+f"((c)[0]), "+f"((c)[1]), "+f"((c)[2]), "+f"((c)[3]) \
                 : "r"(a0), "r"(a1), "r"(a2), "r"(a3), "r"(b0), "r"(b1))

// ---------------------------------------------------------------------------
// Pre-pass 1 (fused): gather+round A, round W (same index space).
// No output zero-fill — the GEMM epilogue writes every element exactly once.
// ---------------------------------------------------------------------------
__global__ void nsl_prep(const float* __restrict__ x,
                         const float* __restrict__ w,
                         const int* __restrict__ in_idx) {
    const int k = blockIdx.x * blockDim.x + threadIdx.x;
    const int m = blockIdx.y;
    const int c = __ldg(&in_idx[k]);
    const size_t i = (size_t)m * ACT_IN + k;
    g_A[i] = __float2half_rn(__ldg(&x[(size_t)m * IN_F + c]));
    g_B[i] = __float2half_rn(__ldg(&w[i]));
}

// Pre-pass 2: inverse output-column map (proven clear+set pair; the R16
// binary-search variant had an off-by-one — 13 bisections leave interval
// length 1, missing actives at lo+1 -> 1.1e-2 error).
__global__ void nsl_inv_clear() {
    g_inv[blockIdx.x * blockDim.x + threadIdx.x] = 0;
}
__global__ void nsl_inv_set(const int* __restrict__ out_idx) {
    const int n = blockIdx.x * blockDim.x + threadIdx.x;
    g_inv[__ldg(&out_idx[n])] = n + 1;
}

// ---------------------------------------------------------------------------
// Main GEMM: single fp16 HMMA product, fp32 register accumulation, 3-stage
// cp.async pipeline, 2 CTAs/SM, dense-stripe epilogue.
// ---------------------------------------------------------------------------
__global__ __launch_bounds__(NTH, 2)
void nsl_mma(const float* __restrict__ bias,
             const int*   __restrict__ out_idx,
             float*       __restrict__ out) {
    extern __shared__ __align__(1024) char smem[];
    const uint32_t sb = smem_u32(smem);
    const int tid  = threadIdx.x;
    const int wid  = tid >> 5;
    const int lane = tid & 31;
    const int m0 = blockIdx.y * BM;
    const int n0 = blockIdx.x * BN;

    const int warp_m = wid >> 2;       // 0..1  -> 64-row slab of M
    const int warp_n = wid & 3;        // 0..3  -> 32-col slab of N

    // ---- cp.async slot mapping: each tile 128 rows x 8 x 16B = 1024 slots ----
    int aG[4]; uint32_t aS[4];
#pragma unroll
    for (int i = 0; i < 4; i++) {
        const int id = tid + i * NTH;
        const int r = id >> 3, cv = id & 7;
        aG[i] = r * ACT_IN + cv * 8;
        aS[i] = SWZ((uint32_t)(r * 128 + cv * 16));
    }
    const __half* pA = g_A + (size_t)m0 * ACT_IN;
    const __half* pB = g_B + (size_t)n0 * ACT_IN;

    auto load_stage = [&](int s) {
        const uint32_t base = sb + (s % NBUF) * STAGE_BYTES;
        const int ke = s * KC;
#pragma unroll
        for (int i = 0; i < 4; i++)
            CPA16(base + T_A + aS[i], pA + ke + aG[i]);
#pragma unroll
        for (int i = 0; i < 4; i++)
            CPA16(base + T_B + aS[i], pB + ke + aG[i]);
        CPA_COMMIT();
    };

    // ---- ldmatrix lane addressing ----
    const int lrow  = lane & 15;
    const uint32_t lkoff = (uint32_t)((lane >> 4) * 16);

    uint32_t aBase[4];
#pragma unroll
    for (int mt = 0; mt < 4; mt++) {
        const int row = warp_m * 64 + mt * 16 + lrow;
        aBase[mt] = (uint32_t)(row * 128) + (((uint32_t)(row & 7)) << 4);
    }
    uint32_t bBase[2];
#pragma unroll
    for (int g = 0; g < 2; g++) {
        const int row = warp_n * 32 + g * 16 + lrow;
        bBase[g] = (uint32_t)(row * 128) + (((uint32_t)(row & 7)) << 4);
    }

    // ---- accumulators: 4 m-tiles x 4 n8-tiles x 4 f32 = 64 regs ----
    float acc[4][4][4];
#pragma unroll
    for (int i = 0; i < 4; i++)
#pragma unroll
        for (int j = 0; j < 4; j++)
#pragma unroll
            for (int q = 0; q < 4; q++) acc[i][j][q] = 0.0f;

    // ---- prologue: 2 stages in flight ----
    load_stage(0);
    load_stage(1);

    for (int s = 0; s < NSTAGE; s++) {
        if (s < NSTAGE - 1) { CPA_WAIT(1); } else { CPA_WAIT(0); }
        __syncthreads();      // also fences compute s-1 (last reader of buf (s+2)%3)

        if (s + 2 < NSTAGE) load_stage(s + 2);

        const uint32_t base = sb + (s % NBUF) * STAGE_BYTES;

#pragma unroll
        for (int ks = 0; ks < 4; ks++) {
            const uint32_t kb = (uint32_t)(ks * 32) + lkoff;

            // A fragments for this k16: 4 m-tiles (16 regs)
            uint32_t ah[4][4];
#pragma unroll
            for (int mt = 0; mt < 4; mt++)
                LDSM4(ah[mt][0], ah[mt][1], ah[mt][2], ah[mt][3],
                      base + T_A + (aBase[mt] ^ kb));

            // B in 2 groups of n16; 4 warps/SMSP cover the LDSM latency
#pragma unroll
            for (int g = 0; g < 2; g++) {
                uint32_t b0, b1, b2, b3;
                LDSM4(b0, b1, b2, b3, base + T_B + (bBase[g] ^ kb));
#pragma unroll
                for (int mt = 0; mt < 4; mt++) {
                    MMA(acc[mt][2*g+0], ah[mt][0], ah[mt][1], ah[mt][2], ah[mt][3], b0, b2);
                    MMA(acc[mt][2*g+1], ah[mt][0], ah[mt][1], ah[mt][2], ah[mt][3], b1, b3);
                }
            }
        }
    }

    // ---- epilogue part 1: stage C (+bias) into smem, pitch-padded ----
    __syncthreads();                   // everyone done reading pipeline smem
    float* sC = (float*)smem;          // [BM][SC_PITCH]

    const int trow = lane >> 2;
    const int tcol = (lane & 3) * 2;
    float bv0[4], bv1[4];
#pragma unroll
    for (int nt = 0; nt < 4; nt++) {
        const int n = n0 + warp_n * 32 + nt * 8 + tcol;
        bv0[nt] = __ldg(&bias[n]);
        bv1[nt] = __ldg(&bias[n + 1]);
    }
#pragma unroll
    for (int mt = 0; mt < 4; mt++) {
        const int r0 = warp_m * 64 + mt * 16 + trow;
        const int r1 = r0 + 8;
#pragma unroll
        for (int nt = 0; nt < 4; nt++) {
            const int c0 = warp_n * 32 + nt * 8 + tcol;
            sC[r0 * SC_PITCH + c0]     = acc[mt][nt][0] + bv0[nt];
            sC[r0 * SC_PITCH + c0 + 1] = acc[mt][nt][1] + bv1[nt];
            sC[r1 * SC_PITCH + c0]     = acc[mt][nt][2] + bv0[nt];
            sC[r1 * SC_PITCH + c0 + 1] = acc[mt][nt][3] + bv1[nt];
        }
    }
    __syncthreads();

    // ---- epilogue part 2: dense stripe sweep, column-major, 8-row batches ----
    const int cStart = (blockIdx.x == 0) ? 0 : __ldg(&out_idx[n0]);
    const int cEnd   = (blockIdx.x == gridDim.x - 1) ? OUT_F
                                                     : __ldg(&out_idx[n0 + BN]);
    for (int c = cStart + tid; c < cEnd; c += NTH) {
        const int nl  = __ldg(&g_inv[c]) - 1 - n0;   // <0 -> inactive
        const bool act = (nl >= 0);
        const float* scol = sC + (act ? nl : 0);     // always-valid address
        float* ocol = out + (size_t)m0 * OUT_F + c;
#pragma unroll 1
        for (int r8 = 0; r8 < BM; r8 += 8) {
            float v[8];
#pragma unroll
            for (int i = 0; i < 8; i++)
                v[i] = scol[(r8 + i) * SC_PITCH];
#pragma unroll
            for (int i = 0; i < 8; i++)
                ocol[(size_t)(r8 + i) * OUT_F] = act ? v[i] : 0.0f;
        }
    }
}

// ---------------------------------------------------------------------------
// Launch
// ---------------------------------------------------------------------------
extern "C" void kernel_launch(void* const* d_in, const int* in_sizes, int n_in,
                              void* d_out, int out_size) {
    const float* x       = (const float*)d_in[0];
    const float* weight  = (const float*)d_in[1];
    const float* bias    = (const float*)d_in[2];
    const int*   in_idx  = (const int*)d_in[3];
    const int*   out_idx = (const int*)d_in[4];
    float* out = (float*)d_out;

    // pre-pass: fused gather+round A / round W, inverse output map
    {
        dim3 g(ACT_IN / 256, NROWS);
        nsl_prep<<<g, 256>>>(x, weight, in_idx);
    }
    nsl_inv_clear<<<OUT_F / 256, 256>>>();
    nsl_inv_set<<<ACT_OUT / 256, 256>>>(out_idx);

    // tensor-core GEMM (mma.sync) + bias + dense-stripe epilogue
    cudaFuncSetAttribute(nsl_mma, cudaFuncAttributeMaxDynamicSharedMemorySize,
                         SMEM_TOTAL);
    dim3 grid(ACT_OUT / BN, NROWS / BM);   // 64 x 64
    nsl_mma<<<grid, NTH, SMEM_TOTAL>>>(bias, out_idx, out);
}